// round 2
// baseline (speedup 1.0000x reference)
#include <cuda_runtime.h>
#include <math.h>

// Problem constants
#define BB   8
#define SS   1040
#define DDIM 1024
#define HH   16
#define HDIM 64
#define PEMB 16
#define MTOT (BB*SS)   // 8320

// Scratch (static device globals; no allocation in kernel_launch)
__device__ float g_q[MTOT*DDIM];
__device__ float g_k[MTOT*DDIM];
__device__ float g_v[MTOT*DDIM];
__device__ float g_o[MTOT*DDIM];

// ---------------------------------------------------------------------------
// Generic C[M=8320,1024] = A[8320,1024] @ W[1024,1024] GEMM
// 64x64 tile, BK=16, 256 threads, 4x4 per-thread microtile, float4 smem loads.
// ---------------------------------------------------------------------------
__global__ __launch_bounds__(256) void gemm64(const float* __restrict__ A,
                                              const float* __restrict__ W,
                                              float* __restrict__ C)
{
    __shared__ float As[16][68];   // [k][m], padded (store-transpose conflicts reduced)
    __shared__ float Bs[16][64];   // [k][n]

    const int m0  = blockIdx.y * 64;
    const int n0  = blockIdx.x * 64;
    const int tid = threadIdx.x;
    const int ty  = tid >> 4;          // 0..15
    const int tx  = tid & 15;          // 0..15
    const int arow = tid >> 2;         // 0..63
    const int akg  = (tid & 3) << 2;   // 0,4,8,12
    const int brow = tid >> 4;         // 0..15
    const int bcol = (tid & 15) << 2;  // 0..60

    float acc[4][4] = {};

    const float* aptr = A + (m0 + arow) * DDIM + akg;
    const float* bptr = W + brow * DDIM + n0 + bcol;

    for (int k0 = 0; k0 < DDIM; k0 += 16) {
        float4 av = *(const float4*)(aptr + k0);
        float4 bv = *(const float4*)(bptr + (size_t)k0 * DDIM);
        As[akg + 0][arow] = av.x;
        As[akg + 1][arow] = av.y;
        As[akg + 2][arow] = av.z;
        As[akg + 3][arow] = av.w;
        *(float4*)&Bs[brow][bcol] = bv;
        __syncthreads();

        #pragma unroll
        for (int kk = 0; kk < 16; kk++) {
            float4 a = *(const float4*)&As[kk][ty << 2];
            float4 b = *(const float4*)&Bs[kk][tx << 2];
            float af[4] = {a.x, a.y, a.z, a.w};
            float bf[4] = {b.x, b.y, b.z, b.w};
            #pragma unroll
            for (int i = 0; i < 4; i++)
                #pragma unroll
                for (int j = 0; j < 4; j++)
                    acc[i][j] = fmaf(af[i], bf[j], acc[i][j]);
        }
        __syncthreads();
    }

    float* cp = C + (m0 + (ty << 2)) * DDIM + n0 + (tx << 2);
    #pragma unroll
    for (int i = 0; i < 4; i++) {
        float4 o = make_float4(acc[i][0], acc[i][1], acc[i][2], acc[i][3]);
        *(float4*)(cp + (size_t)i * DDIM) = o;
    }
}

// ---------------------------------------------------------------------------
// 2D RoPE applied in-place to g_q / g_k for positions s in [16, 1040).
// One thread per (b, pos, h, j) with j in [0,16) handling the 4 coupled lanes.
// ---------------------------------------------------------------------------
__global__ void rope2d()
{
    int idx = blockIdx.x * blockDim.x + threadIdx.x;
    if (idx >= BB * 1024 * HH * 16) return;
    int j   = idx & 15;
    int h   = (idx >> 4) & (HH - 1);
    int pos = (idx >> 8) & 1023;
    int b   = idx >> 18;

    int row = pos >> 5;   // GRID = 32
    int col = pos & 31;

    // timescale = theta^(j/16); angle = pos_component / timescale
    float inv = expf(-(float)j * 0.0625f * 9.210340371976184f); // ln(10000)
    float ar = (float)row * inv;
    float ac = (float)col * inv;
    float rs, rc, cs, cc;
    sincosf(ar, &rs, &rc);
    sincosf(ac, &cs, &cc);

    int s = PEMB + pos;
    int base = ((b * SS + s) * HH + h) * HDIM;

    // q
    {
        float r1 = g_q[base + j];
        float r2 = g_q[base + 16 + j];
        float c1 = g_q[base + 32 + j];
        float c2 = g_q[base + 48 + j];
        g_q[base + j]      = r1 * rc - r2 * rs;
        g_q[base + 16 + j] = r2 * rc + r1 * rs;
        g_q[base + 32 + j] = c1 * cc - c2 * cs;
        g_q[base + 48 + j] = c2 * cc + c1 * cs;
    }
    // k
    {
        float r1 = g_k[base + j];
        float r2 = g_k[base + 16 + j];
        float c1 = g_k[base + 32 + j];
        float c2 = g_k[base + 48 + j];
        g_k[base + j]      = r1 * rc - r2 * rs;
        g_k[base + 16 + j] = r2 * rc + r1 * rs;
        g_k[base + 32 + j] = c1 * cc - c2 * cs;
        g_k[base + 48 + j] = c2 * cc + c1 * cs;
    }
}

// ---------------------------------------------------------------------------
// Flash attention, fp32. Block = 64 queries for one (b,h). 17 key tiles of 64.
// Online softmax; K smem buffer reused for transposed P.
// smem = 3 * 64*64*4 = 48KB exactly.
// ---------------------------------------------------------------------------
__global__ __launch_bounds__(256) void attn_kernel()
{
    __shared__ float Qs[64][64];   // [d][r]  (transposed)
    __shared__ float KP[64][64];   // [d][c] for K, then [k][r] for P
    __shared__ float Vs[64][64];   // [k][d]

    const int qt  = blockIdx.x;
    const int h   = blockIdx.y;
    const int b   = blockIdx.z;
    const int tid = threadIdx.x;
    const int ty  = tid >> 4;
    const int tx  = tid & 15;
    const int lr  = tid >> 4;          // 0..15  loader row base
    const int ld4 = (tid & 15) << 2;   // 0..60  loader d offset

    // Load Q tile transposed (rows beyond S -> 0)
    #pragma unroll
    for (int rr = 0; rr < 4; rr++) {
        int r = lr + rr * 16;
        int s = qt * 64 + r;
        float4 qv = make_float4(0.f, 0.f, 0.f, 0.f);
        if (s < SS)
            qv = *(const float4*)&g_q[((b * SS + s) * HH + h) * HDIM + ld4];
        Qs[ld4 + 0][r] = qv.x;
        Qs[ld4 + 1][r] = qv.y;
        Qs[ld4 + 2][r] = qv.z;
        Qs[ld4 + 3][r] = qv.w;
    }

    float m_i[4], l_i[4], acc[4][4];
    #pragma unroll
    for (int i = 0; i < 4; i++) {
        m_i[i] = -1e30f;
        l_i[i] = 0.f;
        #pragma unroll
        for (int j = 0; j < 4; j++) acc[i][j] = 0.f;
    }
    const float scale = 0.125f; // 1/sqrt(64)

    for (int kt = 0; kt < 17; kt++) {
        // Load K (transposed) and V tiles
        #pragma unroll
        for (int rr = 0; rr < 4; rr++) {
            int r = lr + rr * 16;
            int s = kt * 64 + r;
            float4 kv = make_float4(0.f, 0.f, 0.f, 0.f);
            float4 vv = make_float4(0.f, 0.f, 0.f, 0.f);
            if (s < SS) {
                int base = ((b * SS + s) * HH + h) * HDIM + ld4;
                kv = *(const float4*)&g_k[base];
                vv = *(const float4*)&g_v[base];
            }
            KP[ld4 + 0][r] = kv.x;
            KP[ld4 + 1][r] = kv.y;
            KP[ld4 + 2][r] = kv.z;
            KP[ld4 + 3][r] = kv.w;
            *(float4*)&Vs[r][ld4] = vv;
        }
        __syncthreads();

        // Scores: S = Q @ K^T  (64x64x64)
        float sc[4][4] = {};
        #pragma unroll
        for (int d = 0; d < 64; d++) {
            float4 a = *(const float4*)&Qs[d][ty << 2];
            float4 bq = *(const float4*)&KP[d][tx << 2];
            float af[4] = {a.x, a.y, a.z, a.w};
            float bf[4] = {bq.x, bq.y, bq.z, bq.w};
            #pragma unroll
            for (int i = 0; i < 4; i++)
                #pragma unroll
                for (int j = 0; j < 4; j++)
                    sc[i][j] = fmaf(af[i], bf[j], sc[i][j]);
        }

        #pragma unroll
        for (int i = 0; i < 4; i++)
            #pragma unroll
            for (int j = 0; j < 4; j++)
                sc[i][j] *= scale;

        // Mask invalid keys in last tile (global key = 1024 + 4*tx + j >= 1040)
        if (kt == 16) {
            #pragma unroll
            for (int j = 0; j < 4; j++) {
                int c = (tx << 2) + j;
                if (c >= 16) {
                    #pragma unroll
                    for (int i = 0; i < 4; i++) sc[i][j] = -1e30f;
                }
            }
        }

        // Online softmax update (row reductions across the 16 tx lanes)
        #pragma unroll
        for (int i = 0; i < 4; i++) {
            float mx = fmaxf(fmaxf(sc[i][0], sc[i][1]), fmaxf(sc[i][2], sc[i][3]));
            #pragma unroll
            for (int o = 1; o < 16; o <<= 1)
                mx = fmaxf(mx, __shfl_xor_sync(0xffffffffu, mx, o));
            float mnew = fmaxf(m_i[i], mx);
            float alpha = __expf(m_i[i] - mnew);
            float rs = 0.f;
            #pragma unroll
            for (int j = 0; j < 4; j++) {
                float p = __expf(sc[i][j] - mnew);
                sc[i][j] = p;
                rs += p;
            }
            #pragma unroll
            for (int o = 1; o < 16; o <<= 1)
                rs += __shfl_xor_sync(0xffffffffu, rs, o);
            l_i[i] = l_i[i] * alpha + rs;
            m_i[i] = mnew;
            #pragma unroll
            for (int j = 0; j < 4; j++) acc[i][j] *= alpha;
        }

        __syncthreads();   // done reading KP as K

        // Store P transposed into KP: KP[c][r]
        #pragma unroll
        for (int i = 0; i < 4; i++)
            #pragma unroll
            for (int j = 0; j < 4; j++)
                KP[(tx << 2) + j][(ty << 2) + i] = sc[i][j];
        __syncthreads();

        // acc += P @ V  (64x64x64)
        #pragma unroll
        for (int kk = 0; kk < 64; kk++) {
            float4 p  = *(const float4*)&KP[kk][ty << 2];
            float4 vv = *(const float4*)&Vs[kk][tx << 2];
            float pf[4] = {p.x, p.y, p.z, p.w};
            float vf[4] = {vv.x, vv.y, vv.z, vv.w};
            #pragma unroll
            for (int i = 0; i < 4; i++)
                #pragma unroll
                for (int j = 0; j < 4; j++)
                    acc[i][j] = fmaf(pf[i], vf[j], acc[i][j]);
        }
        __syncthreads();   // before next K/V load
    }

    // Epilogue: out = acc / l
    #pragma unroll
    for (int i = 0; i < 4; i++) {
        int s = qt * 64 + (ty << 2) + i;
        if (s >= SS) continue;
        float invl = 1.0f / l_i[i];
        int base = ((b * SS + s) * HH + h) * HDIM + (tx << 2);
        float4 o = make_float4(acc[i][0] * invl, acc[i][1] * invl,
                               acc[i][2] * invl, acc[i][3] * invl);
        *(float4*)&g_o[base] = o;
    }
}

// ---------------------------------------------------------------------------
extern "C" void kernel_launch(void* const* d_in, const int* in_sizes, int n_in,
                              void* d_out, int out_size)
{
    (void)in_sizes; (void)n_in; (void)out_size;
    const float* x  = (const float*)d_in[0];
    const float* Wq = (const float*)d_in[1];
    const float* Wk = (const float*)d_in[2];
    const float* Wv = (const float*)d_in[3];
    const float* Wo = (const float*)d_in[4];
    float* out = (float*)d_out;

    void *pq, *pk, *pv, *po;
    cudaGetSymbolAddress(&pq, g_q);
    cudaGetSymbolAddress(&pk, g_k);
    cudaGetSymbolAddress(&pv, g_v);
    cudaGetSymbolAddress(&po, g_o);

    dim3 gg(DDIM / 64, MTOT / 64);       // (16, 130)
    gemm64<<<gg, 256>>>(x, Wq, (float*)pq);
    gemm64<<<gg, 256>>>(x, Wk, (float*)pk);
    gemm64<<<gg, 256>>>(x, Wv, (float*)pv);

    int total = BB * 1024 * HH * 16;
    rope2d<<<(total + 255) / 256, 256>>>();

    dim3 ga((SS + 63) / 64, HH, BB);     // (17, 16, 8)
    attn_kernel<<<ga, 256>>>();

    gemm64<<<gg, 256>>>((const float*)po, Wo, out);
}

// round 3
// speedup vs baseline: 1.0003x; 1.0003x over previous
#include <cuda_runtime.h>
#include <math.h>

// Problem constants
#define BB   8
#define SS   1040
#define DDIM 1024
#define HH   16
#define HDIM 64
#define PEMB 16
#define MTOT (BB*SS)   // 8320

// Scratch (static device globals; no allocation in kernel_launch)
__device__ float g_q[MTOT*DDIM];
__device__ float g_k[MTOT*DDIM];
__device__ float g_v[MTOT*DDIM];
__device__ float g_o[MTOT*DDIM];

// ---------------------------------------------------------------------------
// Generic C[M=8320,1024] = A[8320,1024] @ W[1024,1024] GEMM
// 64x64 tile, BK=16, 256 threads, 4x4 per-thread microtile, float4 smem loads.
// ---------------------------------------------------------------------------
__global__ __launch_bounds__(256) void gemm64(const float* __restrict__ A,
                                              const float* __restrict__ W,
                                              float* __restrict__ C)
{
    __shared__ float As[16][68];   // [k][m], padded (store-transpose conflicts reduced)
    __shared__ float Bs[16][64];   // [k][n]

    const int m0  = blockIdx.y * 64;
    const int n0  = blockIdx.x * 64;
    const int tid = threadIdx.x;
    const int ty  = tid >> 4;          // 0..15
    const int tx  = tid & 15;          // 0..15
    const int arow = tid >> 2;         // 0..63
    const int akg  = (tid & 3) << 2;   // 0,4,8,12
    const int brow = tid >> 4;         // 0..15
    const int bcol = (tid & 15) << 2;  // 0..60

    float acc[4][4] = {};

    const float* aptr = A + (m0 + arow) * DDIM + akg;
    const float* bptr = W + brow * DDIM + n0 + bcol;

    for (int k0 = 0; k0 < DDIM; k0 += 16) {
        float4 av = *(const float4*)(aptr + k0);
        float4 bv = *(const float4*)(bptr + (size_t)k0 * DDIM);
        As[akg + 0][arow] = av.x;
        As[akg + 1][arow] = av.y;
        As[akg + 2][arow] = av.z;
        As[akg + 3][arow] = av.w;
        *(float4*)&Bs[brow][bcol] = bv;
        __syncthreads();

        #pragma unroll
        for (int kk = 0; kk < 16; kk++) {
            float4 a = *(const float4*)&As[kk][ty << 2];
            float4 b = *(const float4*)&Bs[kk][tx << 2];
            float af[4] = {a.x, a.y, a.z, a.w};
            float bf[4] = {b.x, b.y, b.z, b.w};
            #pragma unroll
            for (int i = 0; i < 4; i++)
                #pragma unroll
                for (int j = 0; j < 4; j++)
                    acc[i][j] = fmaf(af[i], bf[j], acc[i][j]);
        }
        __syncthreads();
    }

    float* cp = C + (m0 + (ty << 2)) * DDIM + n0 + (tx << 2);
    #pragma unroll
    for (int i = 0; i < 4; i++) {
        float4 o = make_float4(acc[i][0], acc[i][1], acc[i][2], acc[i][3]);
        *(float4*)(cp + (size_t)i * DDIM) = o;
    }
}

// ---------------------------------------------------------------------------
// 2D RoPE applied in-place to g_q / g_k for positions s in [16, 1040).
// One thread per (b, pos, h, j) with j in [0,16) handling the 4 coupled lanes.
// ---------------------------------------------------------------------------
__global__ void rope2d()
{
    int idx = blockIdx.x * blockDim.x + threadIdx.x;
    if (idx >= BB * 1024 * HH * 16) return;
    int j   = idx & 15;
    int h   = (idx >> 4) & (HH - 1);
    int pos = (idx >> 8) & 1023;
    int b   = idx >> 18;

    int row = pos >> 5;   // GRID = 32
    int col = pos & 31;

    // timescale = theta^(j/16); angle = pos_component / timescale
    float inv = expf(-(float)j * 0.0625f * 9.210340371976184f); // ln(10000)
    float ar = (float)row * inv;
    float ac = (float)col * inv;
    float rs, rc, cs, cc;
    sincosf(ar, &rs, &rc);
    sincosf(ac, &cs, &cc);

    int s = PEMB + pos;
    int base = ((b * SS + s) * HH + h) * HDIM;

    // q
    {
        float r1 = g_q[base + j];
        float r2 = g_q[base + 16 + j];
        float c1 = g_q[base + 32 + j];
        float c2 = g_q[base + 48 + j];
        g_q[base + j]      = r1 * rc - r2 * rs;
        g_q[base + 16 + j] = r2 * rc + r1 * rs;
        g_q[base + 32 + j] = c1 * cc - c2 * cs;
        g_q[base + 48 + j] = c2 * cc + c1 * cs;
    }
    // k
    {
        float r1 = g_k[base + j];
        float r2 = g_k[base + 16 + j];
        float c1 = g_k[base + 32 + j];
        float c2 = g_k[base + 48 + j];
        g_k[base + j]      = r1 * rc - r2 * rs;
        g_k[base + 16 + j] = r2 * rc + r1 * rs;
        g_k[base + 32 + j] = c1 * cc - c2 * cs;
        g_k[base + 48 + j] = c2 * cc + c1 * cs;
    }
}

// ---------------------------------------------------------------------------
// Flash attention, fp32. Block = 64 queries for one (b,h). 17 key tiles of 64.
// Online softmax; K smem buffer reused for transposed P.
// smem = 3 * 64*64*4 = 48KB exactly.
// ---------------------------------------------------------------------------
__global__ __launch_bounds__(256) void attn_kernel()
{
    __shared__ float Qs[64][64];   // [d][r]  (transposed)
    __shared__ float KP[64][64];   // [d][c] for K, then [k][r] for P
    __shared__ float Vs[64][64];   // [k][d]

    const int qt  = blockIdx.x;
    const int h   = blockIdx.y;
    const int b   = blockIdx.z;
    const int tid = threadIdx.x;
    const int ty  = tid >> 4;
    const int tx  = tid & 15;
    const int lr  = tid >> 4;          // 0..15  loader row base
    const int ld4 = (tid & 15) << 2;   // 0..60  loader d offset

    // Load Q tile transposed (rows beyond S -> 0)
    #pragma unroll
    for (int rr = 0; rr < 4; rr++) {
        int r = lr + rr * 16;
        int s = qt * 64 + r;
        float4 qv = make_float4(0.f, 0.f, 0.f, 0.f);
        if (s < SS)
            qv = *(const float4*)&g_q[((b * SS + s) * HH + h) * HDIM + ld4];
        Qs[ld4 + 0][r] = qv.x;
        Qs[ld4 + 1][r] = qv.y;
        Qs[ld4 + 2][r] = qv.z;
        Qs[ld4 + 3][r] = qv.w;
    }

    float m_i[4], l_i[4], acc[4][4];
    #pragma unroll
    for (int i = 0; i < 4; i++) {
        m_i[i] = -1e30f;
        l_i[i] = 0.f;
        #pragma unroll
        for (int j = 0; j < 4; j++) acc[i][j] = 0.f;
    }
    const float scale = 0.125f; // 1/sqrt(64)

    for (int kt = 0; kt < 17; kt++) {
        // Load K (transposed) and V tiles
        #pragma unroll
        for (int rr = 0; rr < 4; rr++) {
            int r = lr + rr * 16;
            int s = kt * 64 + r;
            float4 kv = make_float4(0.f, 0.f, 0.f, 0.f);
            float4 vv = make_float4(0.f, 0.f, 0.f, 0.f);
            if (s < SS) {
                int base = ((b * SS + s) * HH + h) * HDIM + ld4;
                kv = *(const float4*)&g_k[base];
                vv = *(const float4*)&g_v[base];
            }
            KP[ld4 + 0][r] = kv.x;
            KP[ld4 + 1][r] = kv.y;
            KP[ld4 + 2][r] = kv.z;
            KP[ld4 + 3][r] = kv.w;
            *(float4*)&Vs[r][ld4] = vv;
        }
        __syncthreads();

        // Scores: S = Q @ K^T  (64x64x64)
        float sc[4][4] = {};
        #pragma unroll
        for (int d = 0; d < 64; d++) {
            float4 a = *(const float4*)&Qs[d][ty << 2];
            float4 bq = *(const float4*)&KP[d][tx << 2];
            float af[4] = {a.x, a.y, a.z, a.w};
            float bf[4] = {bq.x, bq.y, bq.z, bq.w};
            #pragma unroll
            for (int i = 0; i < 4; i++)
                #pragma unroll
                for (int j = 0; j < 4; j++)
                    sc[i][j] = fmaf(af[i], bf[j], sc[i][j]);
        }

        #pragma unroll
        for (int i = 0; i < 4; i++)
            #pragma unroll
            for (int j = 0; j < 4; j++)
                sc[i][j] *= scale;

        // Mask invalid keys in last tile (global key = 1024 + 4*tx + j >= 1040)
        if (kt == 16) {
            #pragma unroll
            for (int j = 0; j < 4; j++) {
                int c = (tx << 2) + j;
                if (c >= 16) {
                    #pragma unroll
                    for (int i = 0; i < 4; i++) sc[i][j] = -1e30f;
                }
            }
        }

        // Online softmax update (row reductions across the 16 tx lanes)
        #pragma unroll
        for (int i = 0; i < 4; i++) {
            float mx = fmaxf(fmaxf(sc[i][0], sc[i][1]), fmaxf(sc[i][2], sc[i][3]));
            #pragma unroll
            for (int o = 1; o < 16; o <<= 1)
                mx = fmaxf(mx, __shfl_xor_sync(0xffffffffu, mx, o));
            float mnew = fmaxf(m_i[i], mx);
            float alpha = __expf(m_i[i] - mnew);
            float rs = 0.f;
            #pragma unroll
            for (int j = 0; j < 4; j++) {
                float p = __expf(sc[i][j] - mnew);
                sc[i][j] = p;
                rs += p;
            }
            #pragma unroll
            for (int o = 1; o < 16; o <<= 1)
                rs += __shfl_xor_sync(0xffffffffu, rs, o);
            l_i[i] = l_i[i] * alpha + rs;
            m_i[i] = mnew;
            #pragma unroll
            for (int j = 0; j < 4; j++) acc[i][j] *= alpha;
        }

        __syncthreads();   // done reading KP as K

        // Store P transposed into KP: KP[c][r]
        #pragma unroll
        for (int i = 0; i < 4; i++)
            #pragma unroll
            for (int j = 0; j < 4; j++)
                KP[(tx << 2) + j][(ty << 2) + i] = sc[i][j];
        __syncthreads();

        // acc += P @ V  (64x64x64)
        #pragma unroll
        for (int kk = 0; kk < 64; kk++) {
            float4 p  = *(const float4*)&KP[kk][ty << 2];
            float4 vv = *(const float4*)&Vs[kk][tx << 2];
            float pf[4] = {p.x, p.y, p.z, p.w};
            float vf[4] = {vv.x, vv.y, vv.z, vv.w};
            #pragma unroll
            for (int i = 0; i < 4; i++)
                #pragma unroll
                for (int j = 0; j < 4; j++)
                    acc[i][j] = fmaf(pf[i], vf[j], acc[i][j]);
        }
        __syncthreads();   // before next K/V load
    }

    // Epilogue: out = acc / l
    #pragma unroll
    for (int i = 0; i < 4; i++) {
        int s = qt * 64 + (ty << 2) + i;
        if (s >= SS) continue;
        float invl = 1.0f / l_i[i];
        int base = ((b * SS + s) * HH + h) * HDIM + (tx << 2);
        float4 o = make_float4(acc[i][0] * invl, acc[i][1] * invl,
                               acc[i][2] * invl, acc[i][3] * invl);
        *(float4*)&g_o[base] = o;
    }
}

// ---------------------------------------------------------------------------
extern "C" void kernel_launch(void* const* d_in, const int* in_sizes, int n_in,
                              void* d_out, int out_size)
{
    (void)in_sizes; (void)n_in; (void)out_size;
    const float* x  = (const float*)d_in[0];
    const float* Wq = (const float*)d_in[1];
    const float* Wk = (const float*)d_in[2];
    const float* Wv = (const float*)d_in[3];
    const float* Wo = (const float*)d_in[4];
    float* out = (float*)d_out;

    void *pq, *pk, *pv, *po;
    cudaGetSymbolAddress(&pq, g_q);
    cudaGetSymbolAddress(&pk, g_k);
    cudaGetSymbolAddress(&pv, g_v);
    cudaGetSymbolAddress(&po, g_o);

    dim3 gg(DDIM / 64, MTOT / 64);       // (16, 130)
    gemm64<<<gg, 256>>>(x, Wq, (float*)pq);
    gemm64<<<gg, 256>>>(x, Wk, (float*)pk);
    gemm64<<<gg, 256>>>(x, Wv, (float*)pv);

    int total = BB * 1024 * HH * 16;
    rope2d<<<(total + 255) / 256, 256>>>();

    dim3 ga((SS + 63) / 64, HH, BB);     // (17, 16, 8)
    attn_kernel<<<ga, 256>>>();

    gemm64<<<gg, 256>>>((const float*)po, Wo, out);
}